// round 8
// baseline (speedup 1.0000x reference)
#include <cuda_runtime.h>
#include <cuda_bf16.h>
#include <cstdint>

#define HH 160
#define WW 160
#define BB 4
#define CC 64
#define COUT 64
#define OFFC 64
#define K2 9
#define HW (HH*WW)             // 25600
#define OUT_MAIN (BB*COUT*HW)  // 6553600
#define OUT_OFF  (BB*2*K2*HW)  // 1843200
#define EPSV 1e-5f

// ---- warp-MMA helpers (plain PTX, works on .target sm_103) ----------------
__device__ __forceinline__ uint32_t smem_u32(const void* p) {
    uint32_t a;
    asm("{ .reg .u64 t; cvta.to.shared.u64 t, %1; cvt.u32.u64 %0, t; }"
        : "=r"(a) : "l"(p));
    return a;
}
__device__ __forceinline__ void ldsm_x4(uint32_t& r0, uint32_t& r1,
                                        uint32_t& r2, uint32_t& r3, uint32_t a) {
    asm volatile("ldmatrix.sync.aligned.m8n8.x4.shared.b16 {%0,%1,%2,%3}, [%4];"
                 : "=r"(r0), "=r"(r1), "=r"(r2), "=r"(r3) : "r"(a));
}
__device__ __forceinline__ void ldsm_x4t(uint32_t& r0, uint32_t& r1,
                                         uint32_t& r2, uint32_t& r3, uint32_t a) {
    asm volatile("ldmatrix.sync.aligned.m8n8.x4.trans.shared.b16 {%0,%1,%2,%3}, [%4];"
                 : "=r"(r0), "=r"(r1), "=r"(r2), "=r"(r3) : "r"(a));
}
__device__ __forceinline__ void mma16816(float* c, const uint32_t* a,
                                         uint32_t b0, uint32_t b1) {
    asm volatile("mma.sync.aligned.m16n8k16.row.col.f32.bf16.bf16.f32 "
                 "{%0,%1,%2,%3}, {%4,%5,%6,%7}, {%8,%9}, {%0,%1,%2,%3};"
                 : "+f"(c[0]), "+f"(c[1]), "+f"(c[2]), "+f"(c[3])
                 : "r"(a[0]), "r"(a[1]), "r"(a[2]), "r"(a[3]), "r"(b0), "r"(b1));
}
__device__ __forceinline__ uint32_t sw128(uint32_t off) {
    return off ^ ((off >> 3) & 0x70);
}
__device__ __forceinline__ uint32_t sw64(uint32_t off) {
    return off ^ ((off >> 3) & 0x30);
}

// ---- global scratch -------------------------------------------------------
__device__ float g_xh[BB*HW*CC];                 // x in NHWC fp32
__device__ float g_dh[BB*HW*CC];                 // d in NHWC fp32
__device__ __nv_bfloat16 g_wbh[K2*CC*COUT];      // conv W hi [tap][cin][cout]
__device__ __nv_bfloat16 g_wbl[K2*CC*COUT];      // conv W lo
__device__ __nv_bfloat16 g_obh[K2*OFFC*32];      // offset W hi [tap][cin][32pad]
__device__ __nv_bfloat16 g_obl[K2*OFFC*32];      // offset W lo
__device__ float g_off[BB*2*K2*HW];              // clamped offsets NCHW
__device__ float g_part[COUT*16*2];
__device__ float g_scale[COUT];
__device__ float g_shift[COUT];

// ---------------------------------------------------------------------------
// NCHW -> NHWC transpose of x (z=0) and d (z=1)
// ---------------------------------------------------------------------------
__global__ void k_transpose(const float* __restrict__ x,
                            const float* __restrict__ d) {
    __shared__ float tile[32][33];
    const float* src = blockIdx.z ? d : x;
    float* dst = blockIdx.z ? g_dh : g_xh;
    int bh = blockIdx.y;
    int b = bh / HH, h = bh % HH;
    int tw = blockIdx.x % 5, tc = blockIdx.x / 5;
    int w = tw * 32 + threadIdx.x;
    #pragma unroll
    for (int i = 0; i < 4; i++) {
        int cl = threadIdx.y + i * 8;
        tile[cl][threadIdx.x] = src[((b*CC + tc*32 + cl)*HH + h)*WW + w];
    }
    __syncthreads();
    #pragma unroll
    for (int i = 0; i < 4; i++) {
        int wl = threadIdx.y + i * 8;
        dst[((b*HH + h)*WW + tw*32 + wl)*CC + tc*32 + threadIdx.x]
            = tile[threadIdx.x][wl];
    }
}

// ---------------------------------------------------------------------------
// Split conv_w into bf16 hi/lo, [tap][cin][cout]
// ---------------------------------------------------------------------------
__global__ void k_wsplit(const float* __restrict__ cw) {
    int i = blockIdx.x * 256 + threadIdx.x;      // K2*CC*COUT = 36864
    if (i < K2*CC*COUT) {
        int tap = i / (CC*COUT), ci = (i / COUT) % CC, co = i % COUT;
        float w = cw[(co*CC + ci)*K2 + tap];
        __nv_bfloat16 h = __float2bfloat16(w);
        float lo = w - __bfloat162float(h);
        g_wbh[i] = h;
        g_wbl[i] = __float2bfloat16(lo);
    }
}

// ---------------------------------------------------------------------------
// Split offset_w into bf16 hi/lo, [tap][cin][32pad] (couts 18..31 zero)
// ---------------------------------------------------------------------------
__global__ void k_owsplit(const float* __restrict__ ow) {
    int i = blockIdx.x * 256 + threadIdx.x;      // K2*OFFC*32 = 18432
    if (i < K2*OFFC*32) {
        int tap = i / (OFFC*32), ci = (i / 32) % OFFC, co = i % 32;
        float w = 0.f;
        if (co < 18) w = ow[(co*OFFC + ci)*K2 + tap];
        __nv_bfloat16 h = __float2bfloat16(w);
        float lo = w - __bfloat162float(h);
        g_obh[i] = h;
        g_obl[i] = __float2bfloat16(lo);
    }
}

// ---------------------------------------------------------------------------
// Offset conv as HMMA GEMM: 256-px tiles, [256px x 576] x [576 x 32(pad18)].
// Warp = M32 x N32 (8 warps). B stored 32-wide, 64B rows, SW64 swizzle.
// ---------------------------------------------------------------------------
#define OSM_A_HI 0
#define OSM_A_LO 32768
#define OSM_B_HI 65536
#define OSM_B_LO 69632
#define OSM_SIZE (73728 + 1024)

__global__ __launch_bounds__(256, 3) void k_offmma(float* __restrict__ outoff) {
    extern __shared__ char smraw[];
    char* sm = (char*)(((uintptr_t)smraw + 1023) & ~(uintptr_t)1023);
    uint32_t s0 = smem_u32(sm);
    int tid = threadIdx.x, wid = tid >> 5, lid = tid & 31;
    int tile = blockIdx.x;            // 0..399
    int b = tile / 100;
    int px0 = (tile % 100) * 256;

    const float4* dp = (const float4*)g_dh;
    int l15 = lid & 15, l16 = (lid >> 4) * 8;
    int g4 = tid & 15, pxl = tid >> 4;

    float acc[2][4][4];
    #pragma unroll
    for (int mt = 0; mt < 2; mt++)
        #pragma unroll
        for (int j = 0; j < 4; j++)
            #pragma unroll
            for (int q = 0; q < 4; q++) acc[mt][j][q] = 0.f;

    for (int tap = 0; tap < 9; tap++) {
        int th = tap / 3 - 1, tw = tap % 3 - 1;
        // ---- shift gather -> A hi/lo (SW128, 256 rows) ----
        #pragma unroll 2
        for (int it = 0; it < 16; it++) {
            int px = pxl + it * 16;
            int pg = px0 + px;
            int h = pg / WW, w = pg - h * WW;
            int y = h + th, x = w + tw;
            float4 v = make_float4(0.f, 0.f, 0.f, 0.f);
            if (y >= 0 && y < HH && x >= 0 && x < WW)
                v = dp[((size_t)((b*HH + y)*WW + x)) * 16 + g4];
            __nv_bfloat162 h01 = __floats2bfloat162_rn(v.x, v.y);
            __nv_bfloat162 h23 = __floats2bfloat162_rn(v.z, v.w);
            __nv_bfloat162 l01 = __floats2bfloat162_rn(
                v.x - __bfloat162float(h01.x), v.y - __bfloat162float(h01.y));
            __nv_bfloat162 l23 = __floats2bfloat162_rn(
                v.z - __bfloat162float(h23.x), v.w - __bfloat162float(h23.y));
            uint32_t sw = sw128(px * 128 + g4 * 8);
            uint2 hv, lv;
            hv.x = *(uint32_t*)&h01; hv.y = *(uint32_t*)&h23;
            lv.x = *(uint32_t*)&l01; lv.y = *(uint32_t*)&l23;
            *(uint2*)(sm + OSM_A_HI + sw) = hv;
            *(uint2*)(sm + OSM_A_LO + sw) = lv;
        }
        // ---- B tile: [64 cin][32 couts], 64B rows, SW64 ----
        {
            const uint4* wh = (const uint4*)g_obh + tap * 256;
            const uint4* wl = (const uint4*)g_obl + tap * 256;
            int row = tid >> 2, q = tid & 3;           // 256 threads = 256 uint4
            uint32_t sw = sw64(row * 64 + q * 16);
            *(uint4*)(sm + OSM_B_HI + sw) = wh[tid];
            *(uint4*)(sm + OSM_B_LO + sw) = wl[tid];
        }
        __syncthreads();

        // ---- MMA: warp wid -> px rows 32wid..+31, couts 0..31 ----
        #pragma unroll
        for (int ks = 0; ks < 4; ks++) {
            int k0 = ks * 16;
            uint32_t ah[2][4], al[2][4];
            #pragma unroll
            for (int mt = 0; mt < 2; mt++) {
                uint32_t sa = sw128((wid*32 + mt*16 + l15) * 128 + (k0 + l16) * 2);
                ldsm_x4(ah[mt][0], ah[mt][1], ah[mt][2], ah[mt][3], s0 + OSM_A_HI + sa);
                ldsm_x4(al[mt][0], al[mt][1], al[mt][2], al[mt][3], s0 + OSM_A_LO + sa);
            }
            #pragma unroll
            for (int jj = 0; jj < 2; jj++) {
                uint32_t sb = sw64((k0 + l15) * 64 + (jj*16 + l16) * 2);
                uint32_t bh0, bh1, bh2, bh3, bl0, bl1, bl2, bl3;
                ldsm_x4t(bh0, bh1, bh2, bh3, s0 + OSM_B_HI + sb);
                ldsm_x4t(bl0, bl1, bl2, bl3, s0 + OSM_B_LO + sb);
                #pragma unroll
                for (int mt = 0; mt < 2; mt++) {
                    mma16816(acc[mt][2*jj],   ah[mt], bh0, bh1);
                    mma16816(acc[mt][2*jj],   ah[mt], bl0, bl1);
                    mma16816(acc[mt][2*jj],   al[mt], bh0, bh1);
                    mma16816(acc[mt][2*jj+1], ah[mt], bh2, bh3);
                    mma16816(acc[mt][2*jj+1], ah[mt], bl2, bl3);
                    mma16816(acc[mt][2*jj+1], al[mt], bh2, bh3);
                }
            }
        }
        __syncthreads();
    }

    // ---- epilogue: clamp + write offsets (NCHW [B,18,H,W]) ----
    #pragma unroll
    for (int mt = 0; mt < 2; mt++) {
        int prow = wid * 32 + mt * 16 + (lid >> 2);
        int pg0 = px0 + prow, pg1 = pg0 + 8;
        #pragma unroll
        for (int j = 0; j < 4; j++) {
            int c0 = j * 8 + (lid & 3) * 2;
            if (c0 < 18) {
                float v0 = fminf(1.f, fmaxf(-1.f, acc[mt][j][0]));
                float v2 = fminf(1.f, fmaxf(-1.f, acc[mt][j][2]));
                int i0 = (b*18 + c0)*HW + pg0;
                int i1 = (b*18 + c0)*HW + pg1;
                g_off[i0] = v0; g_off[i1] = v2;
                if (outoff) { outoff[i0] = v0; outoff[i1] = v2; }
                if (c0 + 1 < 18) {
                    float v1 = fminf(1.f, fmaxf(-1.f, acc[mt][j][1]));
                    float v3 = fminf(1.f, fmaxf(-1.f, acc[mt][j][3]));
                    g_off[i0 + HW] = v1; g_off[i1 + HW] = v3;
                    if (outoff) { outoff[i0 + HW] = v1; outoff[i1 + HW] = v3; }
                }
            }
        }
    }
}

// ---------------------------------------------------------------------------
// Main deformable conv, software-pipelined:
// double-buffered A/B smem, ONE sync per tap; coords via shfl (no smem phase).
// gather(tap+1) + B(tap+1) interleave with MMA(tap) inside each iteration.
// ---------------------------------------------------------------------------
#define DSM_A_HI(buf) ((buf) * 16384)              // 2 x 16KB
#define DSM_A_LO(buf) (32768 + (buf) * 16384)      // 2 x 16KB
#define DSM_B_HI(buf) (65536 + (buf) * 8192)       // 2 x 8KB
#define DSM_B_LO(buf) (81920 + (buf) * 8192)       // 2 x 8KB
#define SM_SIZE (98304 + 1024)

__global__ __launch_bounds__(256, 2) void k_deform(float* __restrict__ out) {
    extern __shared__ char smraw[];
    char* sm = (char*)(((uintptr_t)smraw + 1023) & ~(uintptr_t)1023);
    uint32_t s0 = smem_u32(sm);
    int tid = threadIdx.x, wid = tid >> 5, lid = tid & 31;
    int tile = blockIdx.x;            // 0..799
    int b = tile / 200;
    int px0 = (tile % 200) * 128;

    const float4* xp = (const float4*)g_xh;
    int mw = wid & 3, nw = wid >> 2;
    int l15 = lid & 15, l16 = (lid >> 4) * 8;
    int g4 = lid & 15;
    int src_lane = lid & 16;
    int px_base = 2 * wid + (lid >> 4);   // pixel this lane gathers (per it: +16*it)

    float acc[2][4][4];
    #pragma unroll
    for (int mt = 0; mt < 2; mt++)
        #pragma unroll
        for (int j = 0; j < 4; j++)
            #pragma unroll
            for (int q = 0; q < 4; q++) acc[mt][j][q] = 0.f;

    // ---- gather one tap into buffer buf (coords via shfl) ----
    auto gather_tap = [&](int tap, int buf) {
        #pragma unroll 2
        for (int it = 0; it < 8; it++) {
            int px = px_base + it * 16;
            int cb0, cb1, cb2, cb3;
            float cw0, cw1, cw2, cw3;
            if (g4 == 0) {
                int pg = px0 + px;
                int h = pg / WW, w = pg - h * WW;
                float dy = g_off[(b*18 + 2*tap    )*HW + pg];
                float dx = g_off[(b*18 + 2*tap + 1)*HW + pg];
                float py = (float)h - 1.f + (float)(tap / 3) + dy;
                float pxx = (float)w - 1.f + (float)(tap % 3) + dx;
                float y0f = floorf(py), x0f = floorf(pxx);
                float fy = py - y0f, fx = pxx - x0f;
                int y0 = (int)y0f, x0 = (int)x0f;
                int cb[4]; float cw[4];
                #pragma unroll
                for (int cn = 0; cn < 4; cn++) {
                    int yy = y0 + (cn >> 1), xx = x0 + (cn & 1);
                    float wt = ((cn >> 1) ? fy : 1.f - fy) * ((cn & 1) ? fx : 1.f - fx);
                    bool valid = (yy >= 0) && (yy < HH) && (xx >= 0) && (xx < WW);
                    int yc = min(max(yy, 0), HH - 1), xc = min(max(xx, 0), WW - 1);
                    cb[cn] = ((b*HH + yc)*WW + xc) * CC;
                    cw[cn] = valid ? wt : 0.f;
                }
                cb0 = cb[0]; cb1 = cb[1]; cb2 = cb[2]; cb3 = cb[3];
                cw0 = cw[0]; cw1 = cw[1]; cw2 = cw[2]; cw3 = cw[3];
            }
            cb0 = __shfl_sync(0xffffffffu, cb0, src_lane);
            cb1 = __shfl_sync(0xffffffffu, cb1, src_lane);
            cb2 = __shfl_sync(0xffffffffu, cb2, src_lane);
            cb3 = __shfl_sync(0xffffffffu, cb3, src_lane);
            cw0 = __shfl_sync(0xffffffffu, cw0, src_lane);
            cw1 = __shfl_sync(0xffffffffu, cw1, src_lane);
            cw2 = __shfl_sync(0xffffffffu, cw2, src_lane);
            cw3 = __shfl_sync(0xffffffffu, cw3, src_lane);
            float4 a0 = xp[(cb0 >> 2) + g4];
            float4 a1 = xp[(cb1 >> 2) + g4];
            float4 a2 = xp[(cb2 >> 2) + g4];
            float4 a3 = xp[(cb3 >> 2) + g4];
            float4 v;
            v.x = cw0*a0.x + cw1*a1.x + cw2*a2.x + cw3*a3.x;
            v.y = cw0*a0.y + cw1*a1.y + cw2*a2.y + cw3*a3.y;
            v.z = cw0*a0.z + cw1*a1.z + cw2*a2.z + cw3*a3.z;
            v.w = cw0*a0.w + cw1*a1.w + cw2*a2.w + cw3*a3.w;
            __nv_bfloat162 h01 = __floats2bfloat162_rn(v.x, v.y);
            __nv_bfloat162 h23 = __floats2bfloat162_rn(v.z, v.w);
            __nv_bfloat162 l01 = __floats2bfloat162_rn(
                v.x - __bfloat162float(h01.x), v.y - __bfloat162float(h01.y));
            __nv_bfloat162 l23 = __floats2bfloat162_rn(
                v.z - __bfloat162float(h23.x), v.w - __bfloat162float(h23.y));
            uint32_t sw = sw128(px * 128 + g4 * 8);
            uint2 hv, lv;
            hv.x = *(uint32_t*)&h01; hv.y = *(uint32_t*)&h23;
            lv.x = *(uint32_t*)&l01; lv.y = *(uint32_t*)&l23;
            *(uint2*)(sm + DSM_A_HI(buf) + sw) = hv;
            *(uint2*)(sm + DSM_A_LO(buf) + sw) = lv;
        }
    };
    auto load_b = [&](int tap, int buf) {
        const uint4* wh = (const uint4*)g_wbh + tap * 512;
        const uint4* wl = (const uint4*)g_wbl + tap * 512;
        #pragma unroll
        for (int i = tid; i < 512; i += 256) {
            int row = i >> 3, gq = i & 7;
            uint32_t sw = sw128(row * 128 + gq * 16);
            *(uint4*)(sm + DSM_B_HI(buf) + sw) = wh[i];
            *(uint4*)(sm + DSM_B_LO(buf) + sw) = wl[i];
        }
    };

    // ---- prologue ----
    gather_tap(0, 0);
    load_b(0, 0);
    __syncthreads();

    for (int tap = 0; tap < 9; tap++) {
        int cur = tap & 1, nxt = cur ^ 1;
        // producer work for next tap (interleaves with MMA below)
        if (tap < 8) {
            gather_tap(tap + 1, nxt);
            load_b(tap + 1, nxt);
        }
        // ---- MMA(tap) from buf cur ----
        #pragma unroll
        for (int ks = 0; ks < 4; ks++) {
            int k0 = ks * 16;
            uint32_t ah[2][4], al[2][4];
            #pragma unroll
            for (int mt = 0; mt < 2; mt++) {
                uint32_t sa = sw128((mw*32 + mt*16 + l15) * 128 + (k0 + l16) * 2);
                ldsm_x4(ah[mt][0], ah[mt][1], ah[mt][2], ah[mt][3],
                        s0 + DSM_A_HI(cur) + sa);
                ldsm_x4(al[mt][0], al[mt][1], al[mt][2], al[mt][3],
                        s0 + DSM_A_LO(cur) + sa);
            }
            #pragma unroll
            for (int jj = 0; jj < 2; jj++) {
                uint32_t sb = sw128((k0 + l15) * 128 + (nw*32 + jj*16 + l16) * 2);
                uint32_t bh0, bh1, bh2, bh3, bl0, bl1, bl2, bl3;
                ldsm_x4t(bh0, bh1, bh2, bh3, s0 + DSM_B_HI(cur) + sb);
                ldsm_x4t(bl0, bl1, bl2, bl3, s0 + DSM_B_LO(cur) + sb);
                #pragma unroll
                for (int mt = 0; mt < 2; mt++) {
                    mma16816(acc[mt][2*jj],   ah[mt], bh0, bh1);
                    mma16816(acc[mt][2*jj],   ah[mt], bl0, bl1);
                    mma16816(acc[mt][2*jj],   al[mt], bh0, bh1);
                    mma16816(acc[mt][2*jj+1], ah[mt], bh2, bh3);
                    mma16816(acc[mt][2*jj+1], ah[mt], bl2, bl3);
                    mma16816(acc[mt][2*jj+1], al[mt], bh2, bh3);
                }
            }
        }
        __syncthreads();
    }

    // ---- epilogue: fragments -> NCHW ----
    {
        float* op = out + (size_t)b * COUT * HW;
        #pragma unroll
        for (int mt = 0; mt < 2; mt++) {
            int prow = px0 + mw*32 + mt*16 + (lid >> 2);
            #pragma unroll
            for (int j = 0; j < 4; j++) {
                int c0 = nw*32 + j*8 + (lid & 3) * 2;
                op[(c0    ) * HW + prow    ] = acc[mt][j][0];
                op[(c0 + 1) * HW + prow    ] = acc[mt][j][1];
                op[(c0    ) * HW + prow + 8] = acc[mt][j][2];
                op[(c0 + 1) * HW + prow + 8] = acc[mt][j][3];
            }
        }
    }
}

// ---------------------------------------------------------------------------
// BN stats + apply
// ---------------------------------------------------------------------------
__global__ void k_stats(const float* __restrict__ out) {
    int c = blockIdx.x, bi = blockIdx.y;
    float s = 0.f, sq = 0.f;
    for (int n = bi * 256 + threadIdx.x; n < BB * HW / 4; n += gridDim.y * 256) {
        int b = n / (HW/4), i = n - b * (HW/4);
        float4 v = ((const float4*)(out + (b * COUT + c) * HW))[i];
        s  += v.x + v.y + v.z + v.w;
        sq += v.x*v.x + v.y*v.y + v.z*v.z + v.w*v.w;
    }
    __shared__ float rs[256], rq[256];
    rs[threadIdx.x] = s; rq[threadIdx.x] = sq;
    __syncthreads();
    for (int st = 128; st > 0; st >>= 1) {
        if (threadIdx.x < st) {
            rs[threadIdx.x] += rs[threadIdx.x + st];
            rq[threadIdx.x] += rq[threadIdx.x + st];
        }
        __syncthreads();
    }
    if (threadIdx.x == 0) {
        g_part[(c * 16 + bi) * 2]     = rs[0];
        g_part[(c * 16 + bi) * 2 + 1] = rq[0];
    }
}

__global__ void k_finalize(const float* __restrict__ gamma,
                           const float* __restrict__ beta) {
    int c = threadIdx.x;
    if (c < COUT) {
        float s = 0.f, sq = 0.f;
        for (int i = 0; i < 16; i++) {
            s  += g_part[(c * 16 + i) * 2];
            sq += g_part[(c * 16 + i) * 2 + 1];
        }
        float inv_n = 1.f / (float)(BB * HW);
        float mean = s * inv_n;
        float var  = sq * inv_n - mean * mean;
        float sc = gamma[c] * rsqrtf(var + EPSV);
        g_scale[c] = sc;
        g_shift[c] = beta[c] - mean * sc;
    }
}

__global__ void k_bnrelu(float* __restrict__ out) {
    int idx = blockIdx.x * 256 + threadIdx.x;
    int c = (idx / (HW / 4)) & 63;
    float sc = g_scale[c], sh = g_shift[c];
    float4 v = ((float4*)out)[idx];
    v.x = fmaxf(0.f, v.x * sc + sh);
    v.y = fmaxf(0.f, v.y * sc + sh);
    v.z = fmaxf(0.f, v.z * sc + sh);
    v.w = fmaxf(0.f, v.w * sc + sh);
    ((float4*)out)[idx] = v;
}

// ---------------------------------------------------------------------------
extern "C" void kernel_launch(void* const* d_in, const int* in_sizes, int n_in,
                              void* d_out, int out_size) {
    const float* x     = (const float*)d_in[0];
    const float* d     = (const float*)d_in[1];
    const float* ow    = (const float*)d_in[2];
    const float* cw    = (const float*)d_in[3];
    const float* gamma = (const float*)d_in[4];
    const float* beta  = (const float*)d_in[5];
    float* out = (float*)d_out;
    float* outoff = (out_size >= OUT_MAIN + OUT_OFF) ? (out + OUT_MAIN) : nullptr;

    cudaFuncSetAttribute(k_deform, cudaFuncAttributeMaxDynamicSharedMemorySize,
                         SM_SIZE);
    cudaFuncSetAttribute(k_offmma, cudaFuncAttributeMaxDynamicSharedMemorySize,
                         OSM_SIZE);

    k_transpose<<<dim3(10, BB * HH, 2), dim3(32, 8)>>>(x, d);
    k_wsplit<<<(K2 * CC * COUT + 255) / 256, 256>>>(cw);
    k_owsplit<<<(K2 * OFFC * 32 + 255) / 256, 256>>>(ow);
    k_offmma<<<400, 256, OSM_SIZE>>>(outoff);
    k_deform<<<800, 256, SM_SIZE>>>(out);
    k_stats<<<dim3(COUT, 16), 256>>>(out);
    k_finalize<<<1, 64>>>(gamma, beta);
    k_bnrelu<<<OUT_MAIN / 4 / 256, 256>>>(out);
}

// round 9
// speedup vs baseline: 1.2890x; 1.2890x over previous
#include <cuda_runtime.h>
#include <cuda_bf16.h>
#include <cstdint>

#define HH 160
#define WW 160
#define BB 4
#define CC 64
#define COUT 64
#define OFFC 64
#define K2 9
#define HW (HH*WW)             // 25600
#define OUT_MAIN (BB*COUT*HW)  // 6553600
#define OUT_OFF  (BB*2*K2*HW)  // 1843200
#define NBLK 800
#define EPSV 1e-5f

// ---- warp-MMA helpers (plain PTX, works on .target sm_103) ----------------
__device__ __forceinline__ uint32_t smem_u32(const void* p) {
    uint32_t a;
    asm("{ .reg .u64 t; cvta.to.shared.u64 t, %1; cvt.u32.u64 %0, t; }"
        : "=r"(a) : "l"(p));
    return a;
}
__device__ __forceinline__ void ldsm_x4(uint32_t& r0, uint32_t& r1,
                                        uint32_t& r2, uint32_t& r3, uint32_t a) {
    asm volatile("ldmatrix.sync.aligned.m8n8.x4.shared.b16 {%0,%1,%2,%3}, [%4];"
                 : "=r"(r0), "=r"(r1), "=r"(r2), "=r"(r3) : "r"(a));
}
__device__ __forceinline__ void ldsm_x4t(uint32_t& r0, uint32_t& r1,
                                         uint32_t& r2, uint32_t& r3, uint32_t a) {
    asm volatile("ldmatrix.sync.aligned.m8n8.x4.trans.shared.b16 {%0,%1,%2,%3}, [%4];"
                 : "=r"(r0), "=r"(r1), "=r"(r2), "=r"(r3) : "r"(a));
}
__device__ __forceinline__ void mma16816(float* c, const uint32_t* a,
                                         uint32_t b0, uint32_t b1) {
    asm volatile("mma.sync.aligned.m16n8k16.row.col.f32.bf16.bf16.f32 "
                 "{%0,%1,%2,%3}, {%4,%5,%6,%7}, {%8,%9}, {%0,%1,%2,%3};"
                 : "+f"(c[0]), "+f"(c[1]), "+f"(c[2]), "+f"(c[3])
                 : "r"(a[0]), "r"(a[1]), "r"(a[2]), "r"(a[3]), "r"(b0), "r"(b1));
}
__device__ __forceinline__ uint32_t sw128(uint32_t off) {
    return off ^ ((off >> 3) & 0x70);
}
__device__ __forceinline__ uint32_t sw64(uint32_t off) {
    return off ^ ((off >> 3) & 0x30);
}
__device__ __forceinline__ void cp_async8(uint32_t dst, const void* src, int sz) {
    asm volatile("cp.async.ca.shared.global [%0], [%1], 8, %2;"
                 :: "r"(dst), "l"(src), "r"(sz) : "memory");
}
__device__ __forceinline__ void cp_async16(uint32_t dst, const void* src) {
    asm volatile("cp.async.ca.shared.global [%0], [%1], 16;"
                 :: "r"(dst), "l"(src) : "memory");
}
#define CP_COMMIT() asm volatile("cp.async.commit_group;" ::: "memory")
#define CP_WAIT0()  asm volatile("cp.async.wait_group 0;" ::: "memory")

// ---- global scratch -------------------------------------------------------
__device__ float g_xh[BB*HW*CC];                 // x in NHWC fp32
__device__ __nv_bfloat16 g_dbh[BB*HW*CC];        // d NHWC bf16 hi
__device__ __nv_bfloat16 g_dbl[BB*HW*CC];        // d NHWC bf16 lo
__device__ __nv_bfloat16 g_wbh[K2*CC*COUT];      // conv W hi [tap][cin][cout]
__device__ __nv_bfloat16 g_wbl[K2*CC*COUT];      // conv W lo
__device__ __nv_bfloat16 g_obh[K2*OFFC*32];      // offset W hi [tap][cin][32pad]
__device__ __nv_bfloat16 g_obl[K2*OFFC*32];      // offset W lo
__device__ float g_off[BB*2*K2*HW];              // clamped offsets NCHW
__device__ float g_bs[COUT*NBLK];                // per-block BN sums
__device__ float g_bq[COUT*NBLK];                // per-block BN sumsqs
__device__ float g_scale[COUT];
__device__ float g_shift[COUT];

// ---------------------------------------------------------------------------
// NCHW -> NHWC: x -> fp32 (z=0); d -> bf16 hi/lo (z=1)
// ---------------------------------------------------------------------------
__global__ void k_transpose(const float* __restrict__ x,
                            const float* __restrict__ d) {
    __shared__ float tile[32][33];
    const float* src = blockIdx.z ? d : x;
    int bh = blockIdx.y;
    int b = bh / HH, h = bh % HH;
    int tw = blockIdx.x % 5, tc = blockIdx.x / 5;
    int w = tw * 32 + threadIdx.x;
    #pragma unroll
    for (int i = 0; i < 4; i++) {
        int cl = threadIdx.y + i * 8;
        tile[cl][threadIdx.x] = src[((b*CC + tc*32 + cl)*HH + h)*WW + w];
    }
    __syncthreads();
    #pragma unroll
    for (int i = 0; i < 4; i++) {
        int wl = threadIdx.y + i * 8;
        int idx = ((b*HH + h)*WW + tw*32 + wl)*CC + tc*32 + threadIdx.x;
        float v = tile[threadIdx.x][wl];
        if (blockIdx.z == 0) {
            g_xh[idx] = v;
        } else {
            __nv_bfloat16 hh = __float2bfloat16(v);
            g_dbh[idx] = hh;
            g_dbl[idx] = __float2bfloat16(v - __bfloat162float(hh));
        }
    }
}

// ---------------------------------------------------------------------------
// Split conv_w into bf16 hi/lo, [tap][cin][cout]
// ---------------------------------------------------------------------------
__global__ void k_wsplit(const float* __restrict__ cw) {
    int i = blockIdx.x * 256 + threadIdx.x;      // K2*CC*COUT = 36864
    if (i < K2*CC*COUT) {
        int tap = i / (CC*COUT), ci = (i / COUT) % CC, co = i % COUT;
        float w = cw[(co*CC + ci)*K2 + tap];
        __nv_bfloat16 h = __float2bfloat16(w);
        float lo = w - __bfloat162float(h);
        g_wbh[i] = h;
        g_wbl[i] = __float2bfloat16(lo);
    }
}

// ---------------------------------------------------------------------------
// Split offset_w into bf16 hi/lo, [tap][cin][32pad] (couts 18..31 zero)
// ---------------------------------------------------------------------------
__global__ void k_owsplit(const float* __restrict__ ow) {
    int i = blockIdx.x * 256 + threadIdx.x;      // K2*OFFC*32 = 18432
    if (i < K2*OFFC*32) {
        int tap = i / (OFFC*32), ci = (i / 32) % OFFC, co = i % 32;
        float w = 0.f;
        if (co < 18) w = ow[(co*OFFC + ci)*K2 + tap];
        __nv_bfloat16 h = __float2bfloat16(w);
        float lo = w - __bfloat162float(h);
        g_obh[i] = h;
        g_obl[i] = __float2bfloat16(lo);
    }
}

// ---------------------------------------------------------------------------
// Offset conv as HMMA GEMM: 256-px tiles, [256px x 576] x [576 x 32(pad18)].
// Warp = M32 x N32 (8 warps). A tiles filled by cp.async from pre-split bf16
// (zero-fill OOB), B via cp.async. SW128 A, SW64 B.
// ---------------------------------------------------------------------------
#define OSM_A_HI 0
#define OSM_A_LO 32768
#define OSM_B_HI 65536
#define OSM_B_LO 69632
#define OSM_SIZE (73728 + 1024)

__global__ __launch_bounds__(256, 3) void k_offmma(float* __restrict__ outoff) {
    extern __shared__ char smraw[];
    char* sm = (char*)(((uintptr_t)smraw + 1023) & ~(uintptr_t)1023);
    uint32_t s0 = smem_u32(sm);
    int tid = threadIdx.x, wid = tid >> 5, lid = tid & 31;
    int tile = blockIdx.x;            // 0..399
    int b = tile / 100;
    int px0 = (tile % 100) * 256;

    int l15 = lid & 15, l16 = (lid >> 4) * 8;
    int g4 = tid & 15, pxl = tid >> 4;

    float acc[2][4][4];
    #pragma unroll
    for (int mt = 0; mt < 2; mt++)
        #pragma unroll
        for (int j = 0; j < 4; j++)
            #pragma unroll
            for (int q = 0; q < 4; q++) acc[mt][j][q] = 0.f;

    for (int tap = 0; tap < 9; tap++) {
        int th = tap / 3 - 1, tw = tap % 3 - 1;
        // ---- A: shift copy via cp.async (bf16 hi/lo, zero-fill OOB) ----
        #pragma unroll 4
        for (int it = 0; it < 16; it++) {
            int px = pxl + it * 16;
            int pg = px0 + px;
            int h = pg / WW, w = pg - h * WW;
            int y = h + th, x = w + tw;
            bool valid = (y >= 0) && (y < HH) && (x >= 0) && (x < WW);
            int yc = min(max(y, 0), HH - 1), xc = min(max(x, 0), WW - 1);
            size_t eoff = ((size_t)((b*HH + yc)*WW + xc)) * CC + g4 * 4;
            uint32_t sw = sw128(px * 128 + g4 * 8);
            int sz = valid ? 8 : 0;
            cp_async8(s0 + OSM_A_HI + sw, g_dbh + eoff, sz);
            cp_async8(s0 + OSM_A_LO + sw, g_dbl + eoff, sz);
        }
        // ---- B tile: [64 cin][32 couts], 64B rows, SW64 ----
        {
            const uint4* wh = (const uint4*)g_obh + tap * 256;
            const uint4* wl = (const uint4*)g_obl + tap * 256;
            int row = tid >> 2, q = tid & 3;
            uint32_t sw = sw64(row * 64 + q * 16);
            cp_async16(s0 + OSM_B_HI + sw, wh + tid);
            cp_async16(s0 + OSM_B_LO + sw, wl + tid);
        }
        CP_COMMIT();
        CP_WAIT0();
        __syncthreads();

        // ---- MMA: warp wid -> px rows 32wid..+31, couts 0..31 ----
        #pragma unroll
        for (int ks = 0; ks < 4; ks++) {
            int k0 = ks * 16;
            uint32_t ah[2][4], al[2][4];
            #pragma unroll
            for (int mt = 0; mt < 2; mt++) {
                uint32_t sa = sw128((wid*32 + mt*16 + l15) * 128 + (k0 + l16) * 2);
                ldsm_x4(ah[mt][0], ah[mt][1], ah[mt][2], ah[mt][3], s0 + OSM_A_HI + sa);
                ldsm_x4(al[mt][0], al[mt][1], al[mt][2], al[mt][3], s0 + OSM_A_LO + sa);
            }
            #pragma unroll
            for (int jj = 0; jj < 2; jj++) {
                uint32_t sb = sw64((k0 + l15) * 64 + (jj*16 + l16) * 2);
                uint32_t bh0, bh1, bh2, bh3, bl0, bl1, bl2, bl3;
                ldsm_x4t(bh0, bh1, bh2, bh3, s0 + OSM_B_HI + sb);
                ldsm_x4t(bl0, bl1, bl2, bl3, s0 + OSM_B_LO + sb);
                #pragma unroll
                for (int mt = 0; mt < 2; mt++) {
                    mma16816(acc[mt][2*jj],   ah[mt], bh0, bh1);
                    mma16816(acc[mt][2*jj],   ah[mt], bl0, bl1);
                    mma16816(acc[mt][2*jj],   al[mt], bh0, bh1);
                    mma16816(acc[mt][2*jj+1], ah[mt], bh2, bh3);
                    mma16816(acc[mt][2*jj+1], ah[mt], bl2, bl3);
                    mma16816(acc[mt][2*jj+1], al[mt], bh2, bh3);
                }
            }
        }
        __syncthreads();
    }

    // ---- epilogue: clamp + write offsets (NCHW [B,18,H,W]) ----
    #pragma unroll
    for (int mt = 0; mt < 2; mt++) {
        int prow = wid * 32 + mt * 16 + (lid >> 2);
        int pg0 = px0 + prow, pg1 = pg0 + 8;
        #pragma unroll
        for (int j = 0; j < 4; j++) {
            int c0 = j * 8 + (lid & 3) * 2;
            if (c0 < 18) {
                float v0 = fminf(1.f, fmaxf(-1.f, acc[mt][j][0]));
                float v2 = fminf(1.f, fmaxf(-1.f, acc[mt][j][2]));
                int i0 = (b*18 + c0)*HW + pg0;
                int i1 = (b*18 + c0)*HW + pg1;
                g_off[i0] = v0; g_off[i1] = v2;
                if (outoff) { outoff[i0] = v0; outoff[i1] = v2; }
                if (c0 + 1 < 18) {
                    float v1 = fminf(1.f, fmaxf(-1.f, acc[mt][j][1]));
                    float v3 = fminf(1.f, fmaxf(-1.f, acc[mt][j][3]));
                    g_off[i0 + HW] = v1; g_off[i1 + HW] = v3;
                    if (outoff) { outoff[i0 + HW] = v1; outoff[i1 + HW] = v3; }
                }
            }
        }
    }
}

// ---------------------------------------------------------------------------
// Main deformable conv (R7 structure: 3 syncs/tap, 4 CTAs/SM) + fused BN
// partial-stats reduction in the epilogue.
// ---------------------------------------------------------------------------
#define SM_A_HI 0
#define SM_A_LO 16384
#define SM_B_HI 32768
#define SM_B_LO 40960
#define SM_PBW  49152
#define SM_SIZE (53248 + 1024)

__global__ __launch_bounds__(256, 4) void k_deform(float* __restrict__ out) {
    extern __shared__ char smraw[];
    char* sm = (char*)(((uintptr_t)smraw + 1023) & ~(uintptr_t)1023);
    uint32_t s0 = smem_u32(sm);
    int tid = threadIdx.x, wid = tid >> 5, lid = tid & 31;
    int tile = blockIdx.x;            // 0..799
    int b = tile / 200;
    int px0 = (tile % 200) * 128;

    int2* sBW = (int2*)(sm + SM_PBW);
    const float4* xp = (const float4*)g_xh;

    int mw = wid & 3, nw = wid >> 2;
    int l15 = lid & 15, l16 = (lid >> 4) * 8;

    float acc[2][4][4];
    #pragma unroll
    for (int mt = 0; mt < 2; mt++)
        #pragma unroll
        for (int j = 0; j < 4; j++)
            #pragma unroll
            for (int q = 0; q < 4; q++) acc[mt][j][q] = 0.f;

    for (int tap = 0; tap < 9; tap++) {
        {
            int px = tid >> 1;
            int pg = px0 + px;
            int h = pg / WW, w = pg % WW;
            float dy = g_off[(b*18 + 2*tap    )*HW + pg];
            float dx = g_off[(b*18 + 2*tap + 1)*HW + pg];
            float py = (float)h - 1.f + (float)(tap / 3) + dy;
            float pxx = (float)w - 1.f + (float)(tap % 3) + dx;
            float y0f = floorf(py), x0f = floorf(pxx);
            float fy = py - y0f, fx = pxx - x0f;
            int y0 = (int)y0f, x0 = (int)x0f;
            #pragma unroll
            for (int j = 0; j < 2; j++) {
                int cn = (tid & 1) * 2 + j;
                int yy = y0 + (cn >> 1), xx = x0 + (cn & 1);
                float wt = ((cn >> 1) ? fy : 1.f - fy) * ((cn & 1) ? fx : 1.f - fx);
                bool valid = (yy >= 0) && (yy < HH) && (xx >= 0) && (xx < WW);
                int yc = min(max(yy, 0), HH - 1), xc = min(max(xx, 0), WW - 1);
                sBW[cn*128 + px] = make_int2(((b*HH + yc)*WW + xc) * CC,
                                             __float_as_int(valid ? wt : 0.f));
            }
        }
        __syncthreads();

        {
            int g4 = tid & 15;
            #pragma unroll 2
            for (int it = 0; it < 8; it++) {
                int px = (tid >> 4) + it * 16;
                int2 q0 = sBW[px],       q1 = sBW[128 + px];
                int2 q2 = sBW[256 + px], q3 = sBW[384 + px];
                float w0 = __int_as_float(q0.y), w1 = __int_as_float(q1.y);
                float w2 = __int_as_float(q2.y), w3 = __int_as_float(q3.y);
                float4 a0 = xp[(q0.x >> 2) + g4];
                float4 a1 = xp[(q1.x >> 2) + g4];
                float4 a2 = xp[(q2.x >> 2) + g4];
                float4 a3 = xp[(q3.x >> 2) + g4];
                float4 v;
                v.x = w0*a0.x + w1*a1.x + w2*a2.x + w3*a3.x;
                v.y = w0*a0.y + w1*a1.y + w2*a2.y + w3*a3.y;
                v.z = w0*a0.z + w1*a1.z + w2*a2.z + w3*a3.z;
                v.w = w0*a0.w + w1*a1.w + w2*a2.w + w3*a3.w;
                __nv_bfloat162 h01 = __floats2bfloat162_rn(v.x, v.y);
                __nv_bfloat162 h23 = __floats2bfloat162_rn(v.z, v.w);
                __nv_bfloat162 l01 = __floats2bfloat162_rn(
                    v.x - __bfloat162float(h01.x), v.y - __bfloat162float(h01.y));
                __nv_bfloat162 l23 = __floats2bfloat162_rn(
                    v.z - __bfloat162float(h23.x), v.w - __bfloat162float(h23.y));
                uint32_t sw = sw128(px * 128 + g4 * 8);
                uint2 hv, lv;
                hv.x = *(uint32_t*)&h01; hv.y = *(uint32_t*)&h23;
                lv.x = *(uint32_t*)&l01; lv.y = *(uint32_t*)&l23;
                *(uint2*)(sm + SM_A_HI + sw) = hv;
                *(uint2*)(sm + SM_A_LO + sw) = lv;
            }
        }

        {
            const uint4* wh = (const uint4*)g_wbh + tap * 512;
            const uint4* wl = (const uint4*)g_wbl + tap * 512;
            #pragma unroll
            for (int i = tid; i < 512; i += 256) {
                int row = i >> 3, gq = i & 7;
                uint32_t sw = sw128(row * 128 + gq * 16);
                *(uint4*)(sm + SM_B_HI + sw) = wh[i];
                *(uint4*)(sm + SM_B_LO + sw) = wl[i];
            }
        }
        __syncthreads();

        #pragma unroll
        for (int ks = 0; ks < 4; ks++) {
            int k0 = ks * 16;
            uint32_t ah[2][4], al[2][4];
            #pragma unroll
            for (int mt = 0; mt < 2; mt++) {
                uint32_t sa = sw128((mw*32 + mt*16 + l15) * 128 + (k0 + l16) * 2);
                ldsm_x4(ah[mt][0], ah[mt][1], ah[mt][2], ah[mt][3], s0 + SM_A_HI + sa);
                ldsm_x4(al[mt][0], al[mt][1], al[mt][2], al[mt][3], s0 + SM_A_LO + sa);
            }
            #pragma unroll
            for (int jj = 0; jj < 2; jj++) {
                uint32_t sb = sw128((k0 + l15) * 128 + (nw*32 + jj*16 + l16) * 2);
                uint32_t bh0, bh1, bh2, bh3, bl0, bl1, bl2, bl3;
                ldsm_x4t(bh0, bh1, bh2, bh3, s0 + SM_B_HI + sb);
                ldsm_x4t(bl0, bl1, bl2, bl3, s0 + SM_B_LO + sb);
                #pragma unroll
                for (int mt = 0; mt < 2; mt++) {
                    mma16816(acc[mt][2*jj],   ah[mt], bh0, bh1);
                    mma16816(acc[mt][2*jj],   ah[mt], bl0, bl1);
                    mma16816(acc[mt][2*jj],   al[mt], bh0, bh1);
                    mma16816(acc[mt][2*jj+1], ah[mt], bh2, bh3);
                    mma16816(acc[mt][2*jj+1], ah[mt], bl2, bl3);
                    mma16816(acc[mt][2*jj+1], al[mt], bh2, bh3);
                }
            }
        }
        __syncthreads();
    }

    // ---- epilogue: fragments -> NCHW ----
    {
        float* op = out + (size_t)b * COUT * HW;
        #pragma unroll
        for (int mt = 0; mt < 2; mt++) {
            int prow = px0 + mw*32 + mt*16 + (lid >> 2);
            #pragma unroll
            for (int j = 0; j < 4; j++) {
                int c0 = nw*32 + j*8 + (lid & 3) * 2;
                op[(c0    ) * HW + prow    ] = acc[mt][j][0];
                op[(c0 + 1) * HW + prow    ] = acc[mt][j][1];
                op[(c0    ) * HW + prow + 8] = acc[mt][j][2];
                op[(c0 + 1) * HW + prow + 8] = acc[mt][j][3];
            }
        }
    }

    // ---- fused BN partial stats (deterministic) ----
    {
        float ps[8], pq[8];
        #pragma unroll
        for (int j = 0; j < 4; j++) {
            float s0v = 0.f, s1v = 0.f, q0v = 0.f, q1v = 0.f;
            #pragma unroll
            for (int mt = 0; mt < 2; mt++) {
                float a = acc[mt][j][0], bb = acc[mt][j][1];
                float cvv = acc[mt][j][2], dv = acc[mt][j][3];
                s0v += a + cvv;          s1v += bb + dv;
                q0v += a*a + cvv*cvv;    q1v += bb*bb + dv*dv;
            }
            ps[2*j] = s0v; ps[2*j+1] = s1v;
            pq[2*j] = q0v; pq[2*j+1] = q1v;
        }
        #pragma unroll
        for (int v = 0; v < 8; v++) {
            #pragma unroll
            for (int off = 16; off >= 4; off >>= 1) {
                ps[v] += __shfl_down_sync(0xffffffffu, ps[v], off);
                pq[v] += __shfl_down_sync(0xffffffffu, pq[v], off);
            }
        }
        float* sred = (float*)sm;   // smem free after last tap sync
        if (lid < 4) {
            float* row = sred + wid*64 + lid*16;
            #pragma unroll
            for (int j = 0; j < 4; j++) {
                row[j*4 + 0] = ps[2*j];
                row[j*4 + 1] = ps[2*j + 1];
                row[j*4 + 2] = pq[2*j];
                row[j*4 + 3] = pq[2*j + 1];
            }
        }
        __syncthreads();
        if (tid < 128) {
            int c = tid >> 1, isq = tid & 1;
            int nw2 = c >> 5, local = c & 31;
            int j = local >> 3, l = (local & 7) >> 1, pair = local & 1;
            int idx = l*16 + j*4 + pair + (isq ? 2 : 0);
            float v = sred[(nw2*4 + 0)*64 + idx] + sred[(nw2*4 + 1)*64 + idx]
                    + sred[(nw2*4 + 2)*64 + idx] + sred[(nw2*4 + 3)*64 + idx];
            if (isq) g_bq[c*NBLK + blockIdx.x] = v;
            else     g_bs[c*NBLK + blockIdx.x] = v;
        }
    }
}

// ---------------------------------------------------------------------------
// Finalize BN: one block per channel, reduce 800 partials (deterministic)
// ---------------------------------------------------------------------------
__global__ void k_finalize(const float* __restrict__ gamma,
                           const float* __restrict__ beta) {
    int c = blockIdx.x;
    __shared__ float rs[256], rq[256];
    float s = 0.f, q = 0.f;
    for (int i = threadIdx.x; i < NBLK; i += 256) {
        s += g_bs[c*NBLK + i];
        q += g_bq[c*NBLK + i];
    }
    rs[threadIdx.x] = s; rq[threadIdx.x] = q;
    __syncthreads();
    for (int st = 128; st > 0; st >>= 1) {
        if (threadIdx.x < st) {
            rs[threadIdx.x] += rs[threadIdx.x + st];
            rq[threadIdx.x] += rq[threadIdx.x + st];
        }
        __syncthreads();
    }
    if (threadIdx.x == 0) {
        float inv_n = 1.f / (float)(BB * HW);
        float mean = rs[0] * inv_n;
        float var  = rq[0] * inv_n - mean * mean;
        float sc = gamma[c] * rsqrtf(var + EPSV);
        g_scale[c] = sc;
        g_shift[c] = beta[c] - mean * sc;
    }
}

__global__ void k_bnrelu(float* __restrict__ out) {
    int idx = blockIdx.x * 256 + threadIdx.x;
    int c = (idx / (HW / 4)) & 63;
    float sc = g_scale[c], sh = g_shift[c];
    float4 v = ((float4*)out)[idx];
    v.x = fmaxf(0.f, v.x * sc + sh);
    v.y = fmaxf(0.f, v.y * sc + sh);
    v.z = fmaxf(0.f, v.z * sc + sh);
    v.w = fmaxf(0.f, v.w * sc + sh);
    ((float4*)out)[idx] = v;
}

// ---------------------------------------------------------------------------
extern "C" void kernel_launch(void* const* d_in, const int* in_sizes, int n_in,
                              void* d_out, int out_size) {
    const float* x     = (const float*)d_in[0];
    const float* d     = (const float*)d_in[1];
    const float* ow    = (const float*)d_in[2];
    const float* cw    = (const float*)d_in[3];
    const float* gamma = (const float*)d_in[4];
    const float* beta  = (const float*)d_in[5];
    float* out = (float*)d_out;
    float* outoff = (out_size >= OUT_MAIN + OUT_OFF) ? (out + OUT_MAIN) : nullptr;

    cudaFuncSetAttribute(k_deform, cudaFuncAttributeMaxDynamicSharedMemorySize,
                         SM_SIZE);
    cudaFuncSetAttribute(k_offmma, cudaFuncAttributeMaxDynamicSharedMemorySize,
                         OSM_SIZE);

    k_transpose<<<dim3(10, BB * HH, 2), dim3(32, 8)>>>(x, d);
    k_wsplit<<<(K2 * CC * COUT + 255) / 256, 256>>>(cw);
    k_owsplit<<<(K2 * OFFC * 32 + 255) / 256, 256>>>(ow);
    k_offmma<<<400, 256, OSM_SIZE>>>(outoff);
    k_deform<<<NBLK, 256, SM_SIZE>>>(out);
    k_finalize<<<COUT, 256>>>(gamma, beta);
    k_bnrelu<<<OUT_MAIN / 4 / 256, 256>>>(out);
}

// round 10
// speedup vs baseline: 1.5269x; 1.1845x over previous
#include <cuda_runtime.h>
#include <cuda_bf16.h>
#include <cuda_fp16.h>
#include <cstdint>

#define HH 160
#define WW 160
#define BB 4
#define CC 64
#define COUT 64
#define OFFC 64
#define K2 9
#define HW (HH*WW)             // 25600
#define OUT_MAIN (BB*COUT*HW)  // 6553600
#define OUT_OFF  (BB*2*K2*HW)  // 1843200
#define NBLK 800
#define EPSV 1e-5f

// ---- warp-MMA helpers (plain PTX, works on .target sm_103) ----------------
__device__ __forceinline__ uint32_t smem_u32(const void* p) {
    uint32_t a;
    asm("{ .reg .u64 t; cvta.to.shared.u64 t, %1; cvt.u32.u64 %0, t; }"
        : "=r"(a) : "l"(p));
    return a;
}
__device__ __forceinline__ void ldsm_x4(uint32_t& r0, uint32_t& r1,
                                        uint32_t& r2, uint32_t& r3, uint32_t a) {
    asm volatile("ldmatrix.sync.aligned.m8n8.x4.shared.b16 {%0,%1,%2,%3}, [%4];"
                 : "=r"(r0), "=r"(r1), "=r"(r2), "=r"(r3) : "r"(a));
}
__device__ __forceinline__ void ldsm_x4t(uint32_t& r0, uint32_t& r1,
                                         uint32_t& r2, uint32_t& r3, uint32_t a) {
    asm volatile("ldmatrix.sync.aligned.m8n8.x4.trans.shared.b16 {%0,%1,%2,%3}, [%4];"
                 : "=r"(r0), "=r"(r1), "=r"(r2), "=r"(r3) : "r"(a));
}
__device__ __forceinline__ void mma16816(float* c, const uint32_t* a,
                                         uint32_t b0, uint32_t b1) {
    asm volatile("mma.sync.aligned.m16n8k16.row.col.f32.bf16.bf16.f32 "
                 "{%0,%1,%2,%3}, {%4,%5,%6,%7}, {%8,%9}, {%0,%1,%2,%3};"
                 : "+f"(c[0]), "+f"(c[1]), "+f"(c[2]), "+f"(c[3])
                 : "r"(a[0]), "r"(a[1]), "r"(a[2]), "r"(a[3]), "r"(b0), "r"(b1));
}
__device__ __forceinline__ void mma16816h(float* c, const uint32_t* a,
                                          uint32_t b0, uint32_t b1) {
    asm volatile("mma.sync.aligned.m16n8k16.row.col.f32.f16.f16.f32 "
                 "{%0,%1,%2,%3}, {%4,%5,%6,%7}, {%8,%9}, {%0,%1,%2,%3};"
                 : "+f"(c[0]), "+f"(c[1]), "+f"(c[2]), "+f"(c[3])
                 : "r"(a[0]), "r"(a[1]), "r"(a[2]), "r"(a[3]), "r"(b0), "r"(b1));
}
__device__ __forceinline__ uint32_t sw128(uint32_t off) {
    return off ^ ((off >> 3) & 0x70);
}
__device__ __forceinline__ uint32_t sw64(uint32_t off) {
    return off ^ ((off >> 3) & 0x30);
}
__device__ __forceinline__ void cp_async8(uint32_t dst, const void* src, int sz) {
    asm volatile("cp.async.ca.shared.global [%0], [%1], 8, %2;"
                 :: "r"(dst), "l"(src), "r"(sz) : "memory");
}
__device__ __forceinline__ void cp_async16(uint32_t dst, const void* src) {
    asm volatile("cp.async.ca.shared.global [%0], [%1], 16;"
                 :: "r"(dst), "l"(src) : "memory");
}
#define CP_COMMIT() asm volatile("cp.async.commit_group;" ::: "memory")
#define CP_WAIT0()  asm volatile("cp.async.wait_group 0;" ::: "memory")

// ---- global scratch -------------------------------------------------------
__device__ float g_xh[BB*HW*CC];                 // x in NHWC fp32
__device__ __nv_bfloat16 g_dbh[BB*HW*CC];        // d NHWC bf16 hi
__device__ __nv_bfloat16 g_dbl[BB*HW*CC];        // d NHWC bf16 lo
__device__ __half g_wf[K2*CC*COUT];              // conv W fp16 [tap][cin][cout]
__device__ __nv_bfloat16 g_obh[K2*OFFC*32];      // offset W hi [tap][cin][32pad]
__device__ __nv_bfloat16 g_obl[K2*OFFC*32];      // offset W lo
__device__ float g_off[BB*2*K2*HW];              // clamped offsets NCHW
__device__ float g_bs[COUT*NBLK];                // per-block BN sums
__device__ float g_bq[COUT*NBLK];                // per-block BN sumsqs
__device__ float g_scale[COUT];
__device__ float g_shift[COUT];

// ---------------------------------------------------------------------------
// NCHW -> NHWC: x -> fp32 (z=0); d -> bf16 hi/lo (z=1)
// ---------------------------------------------------------------------------
__global__ void k_transpose(const float* __restrict__ x,
                            const float* __restrict__ d) {
    __shared__ float tile[32][33];
    const float* src = blockIdx.z ? d : x;
    int bh = blockIdx.y;
    int b = bh / HH, h = bh % HH;
    int tw = blockIdx.x % 5, tc = blockIdx.x / 5;
    int w = tw * 32 + threadIdx.x;
    #pragma unroll
    for (int i = 0; i < 4; i++) {
        int cl = threadIdx.y + i * 8;
        tile[cl][threadIdx.x] = src[((b*CC + tc*32 + cl)*HH + h)*WW + w];
    }
    __syncthreads();
    #pragma unroll
    for (int i = 0; i < 4; i++) {
        int wl = threadIdx.y + i * 8;
        int idx = ((b*HH + h)*WW + tw*32 + wl)*CC + tc*32 + threadIdx.x;
        float v = tile[threadIdx.x][wl];
        if (blockIdx.z == 0) {
            g_xh[idx] = v;
        } else {
            __nv_bfloat16 hh = __float2bfloat16(v);
            g_dbh[idx] = hh;
            g_dbl[idx] = __float2bfloat16(v - __bfloat162float(hh));
        }
    }
}

// ---------------------------------------------------------------------------
// conv_w -> fp16, [tap][cin][cout]
// ---------------------------------------------------------------------------
__global__ void k_wsplit(const float* __restrict__ cw) {
    int i = blockIdx.x * 256 + threadIdx.x;      // K2*CC*COUT = 36864
    if (i < K2*CC*COUT) {
        int tap = i / (CC*COUT), ci = (i / COUT) % CC, co = i % COUT;
        g_wf[i] = __float2half(cw[(co*CC + ci)*K2 + tap]);
    }
}

// ---------------------------------------------------------------------------
// Split offset_w into bf16 hi/lo, [tap][cin][32pad] (couts 18..31 zero)
// ---------------------------------------------------------------------------
__global__ void k_owsplit(const float* __restrict__ ow) {
    int i = blockIdx.x * 256 + threadIdx.x;      // K2*OFFC*32 = 18432
    if (i < K2*OFFC*32) {
        int tap = i / (OFFC*32), ci = (i / 32) % OFFC, co = i % 32;
        float w = 0.f;
        if (co < 18) w = ow[(co*OFFC + ci)*K2 + tap];
        __nv_bfloat16 h = __float2bfloat16(w);
        float lo = w - __bfloat162float(h);
        g_obh[i] = h;
        g_obl[i] = __float2bfloat16(lo);
    }
}

// ---------------------------------------------------------------------------
// Offset conv as HMMA GEMM (bf16 hi/lo, unchanged from R9)
// ---------------------------------------------------------------------------
#define OSM_A_HI 0
#define OSM_A_LO 32768
#define OSM_B_HI 65536
#define OSM_B_LO 69632
#define OSM_SIZE (73728 + 1024)

__global__ __launch_bounds__(256, 3) void k_offmma(float* __restrict__ outoff) {
    extern __shared__ char smraw[];
    char* sm = (char*)(((uintptr_t)smraw + 1023) & ~(uintptr_t)1023);
    uint32_t s0 = smem_u32(sm);
    int tid = threadIdx.x, wid = tid >> 5, lid = tid & 31;
    int tile = blockIdx.x;            // 0..399
    int b = tile / 100;
    int px0 = (tile % 100) * 256;

    int l15 = lid & 15, l16 = (lid >> 4) * 8;
    int g4 = tid & 15, pxl = tid >> 4;

    float acc[2][4][4];
    #pragma unroll
    for (int mt = 0; mt < 2; mt++)
        #pragma unroll
        for (int j = 0; j < 4; j++)
            #pragma unroll
            for (int q = 0; q < 4; q++) acc[mt][j][q] = 0.f;

    for (int tap = 0; tap < 9; tap++) {
        int th = tap / 3 - 1, tw = tap % 3 - 1;
        #pragma unroll 4
        for (int it = 0; it < 16; it++) {
            int px = pxl + it * 16;
            int pg = px0 + px;
            int h = pg / WW, w = pg - h * WW;
            int y = h + th, x = w + tw;
            bool valid = (y >= 0) && (y < HH) && (x >= 0) && (x < WW);
            int yc = min(max(y, 0), HH - 1), xc = min(max(x, 0), WW - 1);
            size_t eoff = ((size_t)((b*HH + yc)*WW + xc)) * CC + g4 * 4;
            uint32_t sw = sw128(px * 128 + g4 * 8);
            int sz = valid ? 8 : 0;
            cp_async8(s0 + OSM_A_HI + sw, g_dbh + eoff, sz);
            cp_async8(s0 + OSM_A_LO + sw, g_dbl + eoff, sz);
        }
        {
            const uint4* wh = (const uint4*)g_obh + tap * 256;
            const uint4* wl = (const uint4*)g_obl + tap * 256;
            int row = tid >> 2, q = tid & 3;
            uint32_t sw = sw64(row * 64 + q * 16);
            cp_async16(s0 + OSM_B_HI + sw, wh + tid);
            cp_async16(s0 + OSM_B_LO + sw, wl + tid);
        }
        CP_COMMIT();
        CP_WAIT0();
        __syncthreads();

        #pragma unroll
        for (int ks = 0; ks < 4; ks++) {
            int k0 = ks * 16;
            uint32_t ah[2][4], al[2][4];
            #pragma unroll
            for (int mt = 0; mt < 2; mt++) {
                uint32_t sa = sw128((wid*32 + mt*16 + l15) * 128 + (k0 + l16) * 2);
                ldsm_x4(ah[mt][0], ah[mt][1], ah[mt][2], ah[mt][3], s0 + OSM_A_HI + sa);
                ldsm_x4(al[mt][0], al[mt][1], al[mt][2], al[mt][3], s0 + OSM_A_LO + sa);
            }
            #pragma unroll
            for (int jj = 0; jj < 2; jj++) {
                uint32_t sb = sw64((k0 + l15) * 64 + (jj*16 + l16) * 2);
                uint32_t bh0, bh1, bh2, bh3, bl0, bl1, bl2, bl3;
                ldsm_x4t(bh0, bh1, bh2, bh3, s0 + OSM_B_HI + sb);
                ldsm_x4t(bl0, bl1, bl2, bl3, s0 + OSM_B_LO + sb);
                #pragma unroll
                for (int mt = 0; mt < 2; mt++) {
                    mma16816(acc[mt][2*jj],   ah[mt], bh0, bh1);
                    mma16816(acc[mt][2*jj],   ah[mt], bl0, bl1);
                    mma16816(acc[mt][2*jj],   al[mt], bh0, bh1);
                    mma16816(acc[mt][2*jj+1], ah[mt], bh2, bh3);
                    mma16816(acc[mt][2*jj+1], ah[mt], bl2, bl3);
                    mma16816(acc[mt][2*jj+1], al[mt], bh2, bh3);
                }
            }
        }
        __syncthreads();
    }

    #pragma unroll
    for (int mt = 0; mt < 2; mt++) {
        int prow = wid * 32 + mt * 16 + (lid >> 2);
        int pg0 = px0 + prow, pg1 = pg0 + 8;
        #pragma unroll
        for (int j = 0; j < 4; j++) {
            int c0 = j * 8 + (lid & 3) * 2;
            if (c0 < 18) {
                float v0 = fminf(1.f, fmaxf(-1.f, acc[mt][j][0]));
                float v2 = fminf(1.f, fmaxf(-1.f, acc[mt][j][2]));
                int i0 = (b*18 + c0)*HW + pg0;
                int i1 = (b*18 + c0)*HW + pg1;
                g_off[i0] = v0; g_off[i1] = v2;
                if (outoff) { outoff[i0] = v0; outoff[i1] = v2; }
                if (c0 + 1 < 18) {
                    float v1 = fminf(1.f, fmaxf(-1.f, acc[mt][j][1]));
                    float v3 = fminf(1.f, fmaxf(-1.f, acc[mt][j][3]));
                    g_off[i0 + HW] = v1; g_off[i1 + HW] = v3;
                    if (outoff) { outoff[i0 + HW] = v1; outoff[i1 + HW] = v3; }
                }
            }
        }
    }
}

// ---------------------------------------------------------------------------
// Main deformable conv — single fp16 MMA path (1 MMA per tile, half smem).
// 28KB smem -> higher residency; fused BN partial stats in epilogue.
// ---------------------------------------------------------------------------
#define SM_A   0
#define SM_B   16384
#define SM_PBW 24576
#define SM_SIZE (28672 + 1024)

__global__ __launch_bounds__(256, 4) void k_deform(float* __restrict__ out) {
    extern __shared__ char smraw[];
    char* sm = (char*)(((uintptr_t)smraw + 1023) & ~(uintptr_t)1023);
    uint32_t s0 = smem_u32(sm);
    int tid = threadIdx.x, wid = tid >> 5, lid = tid & 31;
    int tile = blockIdx.x;            // 0..799
    int b = tile / 200;
    int px0 = (tile % 200) * 128;

    int2* sBW = (int2*)(sm + SM_PBW);
    const float4* xp = (const float4*)g_xh;

    int mw = wid & 3, nw = wid >> 2;
    int l15 = lid & 15, l16 = (lid >> 4) * 8;

    float acc[2][4][4];
    #pragma unroll
    for (int mt = 0; mt < 2; mt++)
        #pragma unroll
        for (int j = 0; j < 4; j++)
            #pragma unroll
            for (int q = 0; q < 4; q++) acc[mt][j][q] = 0.f;

    for (int tap = 0; tap < 9; tap++) {
        {
            int px = tid >> 1;
            int pg = px0 + px;
            int h = pg / WW, w = pg % WW;
            float dy = g_off[(b*18 + 2*tap    )*HW + pg];
            float dx = g_off[(b*18 + 2*tap + 1)*HW + pg];
            float py = (float)h - 1.f + (float)(tap / 3) + dy;
            float pxx = (float)w - 1.f + (float)(tap % 3) + dx;
            float y0f = floorf(py), x0f = floorf(pxx);
            float fy = py - y0f, fx = pxx - x0f;
            int y0 = (int)y0f, x0 = (int)x0f;
            #pragma unroll
            for (int j = 0; j < 2; j++) {
                int cn = (tid & 1) * 2 + j;
                int yy = y0 + (cn >> 1), xx = x0 + (cn & 1);
                float wt = ((cn >> 1) ? fy : 1.f - fy) * ((cn & 1) ? fx : 1.f - fx);
                bool valid = (yy >= 0) && (yy < HH) && (xx >= 0) && (xx < WW);
                int yc = min(max(yy, 0), HH - 1), xc = min(max(xx, 0), WW - 1);
                sBW[cn*128 + px] = make_int2(((b*HH + yc)*WW + xc) * CC,
                                             __float_as_int(valid ? wt : 0.f));
            }
        }
        __syncthreads();

        {
            int g4 = tid & 15;
            #pragma unroll 4
            for (int it = 0; it < 8; it++) {
                int px = (tid >> 4) + it * 16;
                int2 q0 = sBW[px],       q1 = sBW[128 + px];
                int2 q2 = sBW[256 + px], q3 = sBW[384 + px];
                float w0 = __int_as_float(q0.y), w1 = __int_as_float(q1.y);
                float w2 = __int_as_float(q2.y), w3 = __int_as_float(q3.y);
                float4 a0 = xp[(q0.x >> 2) + g4];
                float4 a1 = xp[(q1.x >> 2) + g4];
                float4 a2 = xp[(q2.x >> 2) + g4];
                float4 a3 = xp[(q3.x >> 2) + g4];
                float4 v;
                v.x = w0*a0.x + w1*a1.x + w2*a2.x + w3*a3.x;
                v.y = w0*a0.y + w1*a1.y + w2*a2.y + w3*a3.y;
                v.z = w0*a0.z + w1*a1.z + w2*a2.z + w3*a3.z;
                v.w = w0*a0.w + w1*a1.w + w2*a2.w + w3*a3.w;
                __half2 p01 = __floats2half2_rn(v.x, v.y);
                __half2 p23 = __floats2half2_rn(v.z, v.w);
                uint32_t sw = sw128(px * 128 + g4 * 8);
                uint2 hv;
                hv.x = *(uint32_t*)&p01; hv.y = *(uint32_t*)&p23;
                *(uint2*)(sm + SM_A + sw) = hv;
            }
        }

        {
            const uint4* wh = (const uint4*)g_wf + tap * 512;
            #pragma unroll
            for (int i = tid; i < 512; i += 256) {
                int row = i >> 3, gq = i & 7;
                uint32_t sw = sw128(row * 128 + gq * 16);
                *(uint4*)(sm + SM_B + sw) = wh[i];
            }
        }
        __syncthreads();

        #pragma unroll
        for (int ks = 0; ks < 4; ks++) {
            int k0 = ks * 16;
            uint32_t ah[2][4];
            #pragma unroll
            for (int mt = 0; mt < 2; mt++) {
                uint32_t sa = sw128((mw*32 + mt*16 + l15) * 128 + (k0 + l16) * 2);
                ldsm_x4(ah[mt][0], ah[mt][1], ah[mt][2], ah[mt][3], s0 + SM_A + sa);
            }
            #pragma unroll
            for (int jj = 0; jj < 2; jj++) {
                uint32_t sb = sw128((k0 + l15) * 128 + (nw*32 + jj*16 + l16) * 2);
                uint32_t b0, b1, b2, b3;
                ldsm_x4t(b0, b1, b2, b3, s0 + SM_B + sb);
                #pragma unroll
                for (int mt = 0; mt < 2; mt++) {
                    mma16816h(acc[mt][2*jj],   ah[mt], b0, b1);
                    mma16816h(acc[mt][2*jj+1], ah[mt], b2, b3);
                }
            }
        }
        __syncthreads();
    }

    // ---- epilogue: fragments -> NCHW ----
    {
        float* op = out + (size_t)b * COUT * HW;
        #pragma unroll
        for (int mt = 0; mt < 2; mt++) {
            int prow = px0 + mw*32 + mt*16 + (lid >> 2);
            #pragma unroll
            for (int j = 0; j < 4; j++) {
                int c0 = nw*32 + j*8 + (lid & 3) * 2;
                op[(c0    ) * HW + prow    ] = acc[mt][j][0];
                op[(c0 + 1) * HW + prow    ] = acc[mt][j][1];
                op[(c0    ) * HW + prow + 8] = acc[mt][j][2];
                op[(c0 + 1) * HW + prow + 8] = acc[mt][j][3];
            }
        }
    }

    // ---- fused BN partial stats (deterministic) ----
    {
        float ps[8], pq[8];
        #pragma unroll
        for (int j = 0; j < 4; j++) {
            float s0v = 0.f, s1v = 0.f, q0v = 0.f, q1v = 0.f;
            #pragma unroll
            for (int mt = 0; mt < 2; mt++) {
                float a = acc[mt][j][0], bb = acc[mt][j][1];
                float cvv = acc[mt][j][2], dv = acc[mt][j][3];
                s0v += a + cvv;          s1v += bb + dv;
                q0v += a*a + cvv*cvv;    q1v += bb*bb + dv*dv;
            }
            ps[2*j] = s0v; ps[2*j+1] = s1v;
            pq[2*j] = q0v; pq[2*j+1] = q1v;
        }
        #pragma unroll
        for (int v = 0; v < 8; v++) {
            #pragma unroll
            for (int off = 16; off >= 4; off >>= 1) {
                ps[v] += __shfl_down_sync(0xffffffffu, ps[v], off);
                pq[v] += __shfl_down_sync(0xffffffffu, pq[v], off);
            }
        }
        float* sred = (float*)sm;   // smem free after last tap sync
        if (lid < 4) {
            float* row = sred + wid*64 + lid*16;
            #pragma unroll
            for (int j = 0; j < 4; j++) {
                row[j*4 + 0] = ps[2*j];
                row[j*4 + 1] = ps[2*j + 1];
                row[j*4 + 2] = pq[2*j];
                row[j*4 + 3] = pq[2*j + 1];
            }
        }
        __syncthreads();
        if (tid < 128) {
            int c = tid >> 1, isq = tid & 1;
            int nw2 = c >> 5, local = c & 31;
            int j = local >> 3, l = (local & 7) >> 1, pair = local & 1;
            int idx = l*16 + j*4 + pair + (isq ? 2 : 0);
            float v = sred[(nw2*4 + 0)*64 + idx] + sred[(nw2*4 + 1)*64 + idx]
                    + sred[(nw2*4 + 2)*64 + idx] + sred[(nw2*4 + 3)*64 + idx];
            if (isq) g_bq[c*NBLK + blockIdx.x] = v;
            else     g_bs[c*NBLK + blockIdx.x] = v;
        }
    }
}

// ---------------------------------------------------------------------------
// Finalize BN: one block per channel, reduce 800 partials (deterministic)
// ---------------------------------------------------------------------------
__global__ void k_finalize(const float* __restrict__ gamma,
                           const float* __restrict__ beta) {
    int c = blockIdx.x;
    __shared__ float rs[256], rq[256];
    float s = 0.f, q = 0.f;
    for (int i = threadIdx.x; i < NBLK; i += 256) {
        s += g_bs[c*NBLK + i];
        q += g_bq[c*NBLK + i];
    }
    rs[threadIdx.x] = s; rq[threadIdx.x] = q;
    __syncthreads();
    for (int st = 128; st > 0; st >>= 1) {
        if (threadIdx.x < st) {
            rs[threadIdx.x] += rs[threadIdx.x + st];
            rq[threadIdx.x] += rq[threadIdx.x + st];
        }
        __syncthreads();
    }
    if (threadIdx.x == 0) {
        float inv_n = 1.f / (float)(BB * HW);
        float mean = rs[0] * inv_n;
        float var  = rq[0] * inv_n - mean * mean;
        float sc = gamma[c] * rsqrtf(var + EPSV);
        g_scale[c] = sc;
        g_shift[c] = beta[c] - mean * sc;
    }
}

__global__ void k_bnrelu(float* __restrict__ out) {
    int idx = blockIdx.x * 256 + threadIdx.x;
    int c = (idx / (HW / 4)) & 63;
    float sc = g_scale[c], sh = g_shift[c];
    float4 v = ((float4*)out)[idx];
    v.x = fmaxf(0.f, v.x * sc + sh);
    v.y = fmaxf(0.f, v.y * sc + sh);
    v.z = fmaxf(0.f, v.z * sc + sh);
    v.w = fmaxf(0.f, v.w * sc + sh);
    ((float4*)out)[idx] = v;
}

// ---------------------------------------------------------------------------
extern "C" void kernel_launch(void* const* d_in, const int* in_sizes, int n_in,
                              void* d_out, int out_size) {
    const float* x     = (const float*)d_in[0];
    const float* d     = (const float*)d_in[1];
    const float* ow    = (const float*)d_in[2];
    const float* cw    = (const float*)d_in[3];
    const float* gamma = (const float*)d_in[4];
    const float* beta  = (const float*)d_in[5];
    float* out = (float*)d_out;
    float* outoff = (out_size >= OUT_MAIN + OUT_OFF) ? (out + OUT_MAIN) : nullptr;

    cudaFuncSetAttribute(k_deform, cudaFuncAttributeMaxDynamicSharedMemorySize,
                         SM_SIZE);
    cudaFuncSetAttribute(k_offmma, cudaFuncAttributeMaxDynamicSharedMemorySize,
                         OSM_SIZE);

    k_transpose<<<dim3(10, BB * HH, 2), dim3(32, 8)>>>(x, d);
    k_wsplit<<<(K2 * CC * COUT + 255) / 256, 256>>>(cw);
    k_owsplit<<<(K2 * OFFC * 32 + 255) / 256, 256>>>(ow);
    k_offmma<<<400, 256, OSM_SIZE>>>(outoff);
    k_deform<<<NBLK, 256, SM_SIZE>>>(out);
    k_finalize<<<COUT, 256>>>(gamma, beta);
    k_bnrelu<<<OUT_MAIN / 4 / 256, 256>>>(out);
}

// round 13
// speedup vs baseline: 1.8317x; 1.1996x over previous
#include <cuda_runtime.h>
#include <cuda_bf16.h>
#include <cuda_fp16.h>
#include <cstdint>

#define HH 160
#define WW 160
#define BB 4
#define CC 64
#define COUT 64
#define OFFC 64
#define K2 9
#define HW (HH*WW)             // 25600
#define OUT_MAIN (BB*COUT*HW)  // 6553600
#define OUT_OFF  (BB*2*K2*HW)  // 1843200
#define NBLK 800
#define EPSV 1e-5f

// ---- warp-MMA helpers (plain PTX, works on .target sm_103) ----------------
__device__ __forceinline__ uint32_t smem_u32(const void* p) {
    uint32_t a;
    asm("{ .reg .u64 t; cvta.to.shared.u64 t, %1; cvt.u32.u64 %0, t; }"
        : "=r"(a) : "l"(p));
    return a;
}
__device__ __forceinline__ void ldsm_x4(uint32_t& r0, uint32_t& r1,
                                        uint32_t& r2, uint32_t& r3, uint32_t a) {
    asm volatile("ldmatrix.sync.aligned.m8n8.x4.shared.b16 {%0,%1,%2,%3}, [%4];"
                 : "=r"(r0), "=r"(r1), "=r"(r2), "=r"(r3) : "r"(a));
}
__device__ __forceinline__ void ldsm_x4t(uint32_t& r0, uint32_t& r1,
                                         uint32_t& r2, uint32_t& r3, uint32_t a) {
    asm volatile("ldmatrix.sync.aligned.m8n8.x4.trans.shared.b16 {%0,%1,%2,%3}, [%4];"
                 : "=r"(r0), "=r"(r1), "=r"(r2), "=r"(r3) : "r"(a));
}
__device__ __forceinline__ void mma16816h(float* c, const uint32_t* a,
                                          uint32_t b0, uint32_t b1) {
    asm volatile("mma.sync.aligned.m16n8k16.row.col.f32.f16.f16.f32 "
                 "{%0,%1,%2,%3}, {%4,%5,%6,%7}, {%8,%9}, {%0,%1,%2,%3};"
                 : "+f"(c[0]), "+f"(c[1]), "+f"(c[2]), "+f"(c[3])
                 : "r"(a[0]), "r"(a[1]), "r"(a[2]), "r"(a[3]), "r"(b0), "r"(b1));
}
__device__ __forceinline__ uint32_t sw128(uint32_t off) {
    return off ^ ((off >> 3) & 0x70);
}
__device__ __forceinline__ uint32_t sw64(uint32_t off) {
    return off ^ ((off >> 3) & 0x30);
}
__device__ __forceinline__ void cp_async8(uint32_t dst, const void* src, int sz) {
    asm volatile("cp.async.ca.shared.global [%0], [%1], 8, %2;"
                 :: "r"(dst), "l"(src), "r"(sz) : "memory");
}
__device__ __forceinline__ void cp_async16(uint32_t dst, const void* src) {
    asm volatile("cp.async.ca.shared.global [%0], [%1], 16;"
                 :: "r"(dst), "l"(src) : "memory");
}
#define CP_COMMIT() asm volatile("cp.async.commit_group;" ::: "memory")
#define CP_WAIT0()  asm volatile("cp.async.wait_group 0;" ::: "memory")

// ---- global scratch -------------------------------------------------------
__device__ __half g_xf[BB*HW*CC];                // x NHWC fp16
__device__ __half g_df[BB*HW*CC];                // d NHWC fp16
__device__ __half g_wf[K2*CC*COUT];              // conv W fp16 [tap][cin][cout]
__device__ __half g_ofw[K2*OFFC*32];             // offset W fp16 [tap][cin][32pad]
__device__ float g_off[BB*2*K2*HW];              // clamped offsets NCHW
__device__ float g_bs[COUT*NBLK];                // per-block BN sums
__device__ float g_bq[COUT*NBLK];                // per-block BN sumsqs
__device__ float g_scale[COUT];
__device__ float g_shift[COUT];

// ---------------------------------------------------------------------------
// NCHW -> NHWC fp16: x (z=0), d (z=1)
// ---------------------------------------------------------------------------
__global__ void k_transpose(const float* __restrict__ x,
                            const float* __restrict__ d) {
    __shared__ float tile[32][33];
    const float* src = blockIdx.z ? d : x;
    __half* dst = blockIdx.z ? g_df : g_xf;
    int bh = blockIdx.y;
    int b = bh / HH, h = bh % HH;
    int tw = blockIdx.x % 5, tc = blockIdx.x / 5;
    int w = tw * 32 + threadIdx.x;
    #pragma unroll
    for (int i = 0; i < 4; i++) {
        int cl = threadIdx.y + i * 8;
        tile[cl][threadIdx.x] = src[((b*CC + tc*32 + cl)*HH + h)*WW + w];
    }
    __syncthreads();
    #pragma unroll
    for (int i = 0; i < 4; i++) {
        int wl = threadIdx.y + i * 8;
        int idx = ((b*HH + h)*WW + tw*32 + wl)*CC + tc*32 + threadIdx.x;
        dst[idx] = __float2half(tile[threadIdx.x][wl]);
    }
}

// ---------------------------------------------------------------------------
// conv_w -> fp16, [tap][cin][cout]
// ---------------------------------------------------------------------------
__global__ void k_wsplit(const float* __restrict__ cw) {
    int i = blockIdx.x * 256 + threadIdx.x;      // K2*CC*COUT = 36864
    if (i < K2*CC*COUT) {
        int tap = i / (CC*COUT), ci = (i / COUT) % CC, co = i % COUT;
        g_wf[i] = __float2half(cw[(co*CC + ci)*K2 + tap]);
    }
}

// ---------------------------------------------------------------------------
// offset_w -> fp16, [tap][cin][32pad] (couts 18..31 zero)
// ---------------------------------------------------------------------------
__global__ void k_owsplit(const float* __restrict__ ow) {
    int i = blockIdx.x * 256 + threadIdx.x;      // K2*OFFC*32 = 18432
    if (i < K2*OFFC*32) {
        int tap = i / (OFFC*32), ci = (i / 32) % OFFC, co = i % 32;
        float w = 0.f;
        if (co < 18) w = ow[(co*OFFC + ci)*K2 + tap];
        g_ofw[i] = __float2half(w);
    }
}

// ---------------------------------------------------------------------------
// Offset conv as single-fp16 HMMA GEMM: 256-px tiles, warp = M32 x N32.
// A via cp.async from fp16 d (zero-fill OOB), B fp16 SW64.
// ---------------------------------------------------------------------------
#define OSM_A 0
#define OSM_B 32768
#define OSM_SIZE (36864 + 1024)

__global__ __launch_bounds__(256, 4) void k_offmma(float* __restrict__ outoff) {
    extern __shared__ char smraw[];
    char* sm = (char*)(((uintptr_t)smraw + 1023) & ~(uintptr_t)1023);
    uint32_t s0 = smem_u32(sm);
    int tid = threadIdx.x, wid = tid >> 5, lid = tid & 31;
    int tile = blockIdx.x;            // 0..399
    int b = tile / 100;
    int px0 = (tile % 100) * 256;

    int l15 = lid & 15, l16 = (lid >> 4) * 8;
    int g4 = tid & 15, pxl = tid >> 4;

    float acc[2][4][4];
    #pragma unroll
    for (int mt = 0; mt < 2; mt++)
        #pragma unroll
        for (int j = 0; j < 4; j++)
            #pragma unroll
            for (int q = 0; q < 4; q++) acc[mt][j][q] = 0.f;

    for (int tap = 0; tap < 9; tap++) {
        int th = tap / 3 - 1, tw = tap % 3 - 1;
        // ---- A: shift copy via cp.async (fp16, zero-fill OOB) ----
        #pragma unroll 4
        for (int it = 0; it < 16; it++) {
            int px = pxl + it * 16;
            int pg = px0 + px;
            int h = pg / WW, w = pg - h * WW;
            int y = h + th, x = w + tw;
            bool valid = (y >= 0) && (y < HH) && (x >= 0) && (x < WW);
            int yc = min(max(y, 0), HH - 1), xc = min(max(x, 0), WW - 1);
            size_t eoff = ((size_t)((b*HH + yc)*WW + xc)) * CC + g4 * 4;
            uint32_t sw = sw128(px * 128 + g4 * 8);
            cp_async8(s0 + OSM_A + sw, g_df + eoff, valid ? 8 : 0);
        }
        // ---- B tile: [64 cin][32 couts], 64B rows, SW64 ----
        {
            const uint4* wp = (const uint4*)g_ofw + tap * 256;
            int row = tid >> 2, q = tid & 3;
            uint32_t sw = sw64(row * 64 + q * 16);
            cp_async16(s0 + OSM_B + sw, wp + tid);
        }
        CP_COMMIT();
        CP_WAIT0();
        __syncthreads();

        // ---- MMA: warp wid -> px rows 32wid..+31, couts 0..31 ----
        #pragma unroll
        for (int ks = 0; ks < 4; ks++) {
            int k0 = ks * 16;
            uint32_t ah[2][4];
            #pragma unroll
            for (int mt = 0; mt < 2; mt++) {
                uint32_t sa = sw128((wid*32 + mt*16 + l15) * 128 + (k0 + l16) * 2);
                ldsm_x4(ah[mt][0], ah[mt][1], ah[mt][2], ah[mt][3], s0 + OSM_A + sa);
            }
            #pragma unroll
            for (int jj = 0; jj < 2; jj++) {
                uint32_t sb = sw64((k0 + l15) * 64 + (jj*16 + l16) * 2);
                uint32_t b0, b1, b2, b3;
                ldsm_x4t(b0, b1, b2, b3, s0 + OSM_B + sb);
                #pragma unroll
                for (int mt = 0; mt < 2; mt++) {
                    mma16816h(acc[mt][2*jj],   ah[mt], b0, b1);
                    mma16816h(acc[mt][2*jj+1], ah[mt], b2, b3);
                }
            }
        }
        __syncthreads();
    }

    // ---- epilogue: clamp + write offsets (NCHW [B,18,H,W]) ----
    #pragma unroll
    for (int mt = 0; mt < 2; mt++) {
        int prow = wid * 32 + mt * 16 + (lid >> 2);
        int pg0 = px0 + prow, pg1 = pg0 + 8;
        #pragma unroll
        for (int j = 0; j < 4; j++) {
            int c0 = j * 8 + (lid & 3) * 2;
            if (c0 < 18) {
                float v0 = fminf(1.f, fmaxf(-1.f, acc[mt][j][0]));
                float v2 = fminf(1.f, fmaxf(-1.f, acc[mt][j][2]));
                int i0 = (b*18 + c0)*HW + pg0;
                int i1 = (b*18 + c0)*HW + pg1;
                g_off[i0] = v0; g_off[i1] = v2;
                if (outoff) { outoff[i0] = v0; outoff[i1] = v2; }
                if (c0 + 1 < 18) {
                    float v1 = fminf(1.f, fmaxf(-1.f, acc[mt][j][1]));
                    float v3 = fminf(1.f, fmaxf(-1.f, acc[mt][j][3]));
                    g_off[i0 + HW] = v1; g_off[i1 + HW] = v3;
                    if (outoff) { outoff[i0 + HW] = v1; outoff[i1 + HW] = v3; }
                }
            }
        }
    }
}

// ---------------------------------------------------------------------------
// Main deformable conv — fp16 MMA; x gathered as fp16 (halved L1 traffic),
// bilinear accumulated in fp32. Fused BN partial stats in epilogue.
// ---------------------------------------------------------------------------
#define SM_A   0
#define SM_B   16384
#define SM_PBW 24576
#define SM_SIZE (28672 + 1024)

__global__ __launch_bounds__(256, 4) void k_deform(float* __restrict__ out) {
    extern __shared__ char smraw[];
    char* sm = (char*)(((uintptr_t)smraw + 1023) & ~(uintptr_t)1023);
    uint32_t s0 = smem_u32(sm);
    int tid = threadIdx.x, wid = tid >> 5, lid = tid & 31;
    int tile = blockIdx.x;            // 0..799
    int b = tile / 200;
    int px0 = (tile % 200) * 128;

    int2* sBW = (int2*)(sm + SM_PBW);
    const __half2* xp = (const __half2*)g_xf;

    int mw = wid & 3, nw = wid >> 2;
    int l15 = lid & 15, l16 = (lid >> 4) * 8;

    float acc[2][4][4];
    #pragma unroll
    for (int mt = 0; mt < 2; mt++)
        #pragma unroll
        for (int j = 0; j < 4; j++)
            #pragma unroll
            for (int q = 0; q < 4; q++) acc[mt][j][q] = 0.f;

    for (int tap = 0; tap < 9; tap++) {
        {
            int px = tid >> 1;
            int pg = px0 + px;
            int h = pg / WW, w = pg % WW;
            float dy = g_off[(b*18 + 2*tap    )*HW + pg];
            float dx = g_off[(b*18 + 2*tap + 1)*HW + pg];
            float py = (float)h - 1.f + (float)(tap / 3) + dy;
            float pxx = (float)w - 1.f + (float)(tap % 3) + dx;
            float y0f = floorf(py), x0f = floorf(pxx);
            float fy = py - y0f, fx = pxx - x0f;
            int y0 = (int)y0f, x0 = (int)x0f;
            #pragma unroll
            for (int j = 0; j < 2; j++) {
                int cn = (tid & 1) * 2 + j;
                int yy = y0 + (cn >> 1), xx = x0 + (cn & 1);
                float wt = ((cn >> 1) ? fy : 1.f - fy) * ((cn & 1) ? fx : 1.f - fx);
                bool valid = (yy >= 0) && (yy < HH) && (xx >= 0) && (xx < WW);
                int yc = min(max(yy, 0), HH - 1), xc = min(max(xx, 0), WW - 1);
                sBW[cn*128 + px] = make_int2(((b*HH + yc)*WW + xc) * CC,
                                             __float_as_int(valid ? wt : 0.f));
            }
        }
        __syncthreads();

        {
            int g4 = tid & 15;
            #pragma unroll 4
            for (int it = 0; it < 8; it++) {
                int px = (tid >> 4) + it * 16;
                int2 q0 = sBW[px],       q1 = sBW[128 + px];
                int2 q2 = sBW[256 + px], q3 = sBW[384 + px];
                float w0 = __int_as_float(q0.y), w1 = __int_as_float(q1.y);
                float w2 = __int_as_float(q2.y), w3 = __int_as_float(q3.y);
                // 4 channels per thread = 2 half2 loads per corner (8B)
                int i0 = (q0.x >> 1) + g4*2, i1 = (q1.x >> 1) + g4*2;
                int i2 = (q2.x >> 1) + g4*2, i3 = (q3.x >> 1) + g4*2;
                float2 a0x = __half22float2(xp[i0]),   a0y = __half22float2(xp[i0+1]);
                float2 a1x = __half22float2(xp[i1]),   a1y = __half22float2(xp[i1+1]);
                float2 a2x = __half22float2(xp[i2]),   a2y = __half22float2(xp[i2+1]);
                float2 a3x = __half22float2(xp[i3]),   a3y = __half22float2(xp[i3+1]);
                float4 v;
                v.x = w0*a0x.x + w1*a1x.x + w2*a2x.x + w3*a3x.x;
                v.y = w0*a0x.y + w1*a1x.y + w2*a2x.y + w3*a3x.y;
                v.z = w0*a0y.x + w1*a1y.x + w2*a2y.x + w3*a3y.x;
                v.w = w0*a0y.y + w1*a1y.y + w2*a2y.y + w3*a3y.y;
                __half2 p01 = __floats2half2_rn(v.x, v.y);
                __half2 p23 = __floats2half2_rn(v.z, v.w);
                uint32_t sw = sw128(px * 128 + g4 * 8);
                uint2 hv;
                hv.x = *(uint32_t*)&p01; hv.y = *(uint32_t*)&p23;
                *(uint2*)(sm + SM_A + sw) = hv;
            }
        }

        {
            const uint4* wh = (const uint4*)g_wf + tap * 512;
            #pragma unroll
            for (int i = tid; i < 512; i += 256) {
                int row = i >> 3, gq = i & 7;
                uint32_t sw = sw128(row * 128 + gq * 16);
                *(uint4*)(sm + SM_B + sw) = wh[i];
            }
        }
        __syncthreads();

        #pragma unroll
        for (int ks = 0; ks < 4; ks++) {
            int k0 = ks * 16;
            uint32_t ah[2][4];
            #pragma unroll
            for (int mt = 0; mt < 2; mt++) {
                uint32_t sa = sw128((mw*32 + mt*16 + l15) * 128 + (k0 + l16) * 2);
                ldsm_x4(ah[mt][0], ah[mt][1], ah[mt][2], ah[mt][3], s0 + SM_A + sa);
            }
            #pragma unroll
            for (int jj = 0; jj < 2; jj++) {
                uint32_t sb = sw128((k0 + l15) * 128 + (nw*32 + jj*16 + l16) * 2);
                uint32_t b0, b1, b2, b3;
                ldsm_x4t(b0, b1, b2, b3, s0 + SM_B + sb);
                #pragma unroll
                for (int mt = 0; mt < 2; mt++) {
                    mma16816h(acc[mt][2*jj],   ah[mt], b0, b1);
                    mma16816h(acc[mt][2*jj+1], ah[mt], b2, b3);
                }
            }
        }
        __syncthreads();
    }

    // ---- epilogue: fragments -> NCHW ----
    {
        float* op = out + (size_t)b * COUT * HW;
        #pragma unroll
        for (int mt = 0; mt < 2; mt++) {
            int prow = px0 + mw*32 + mt*16 + (lid >> 2);
            #pragma unroll
            for (int j = 0; j < 4; j++) {
                int c0 = nw*32 + j*8 + (lid & 3) * 2;
                op[(c0    ) * HW + prow    ] = acc[mt][j][0];
                op[(c0 + 1) * HW + prow    ] = acc[mt][j][1];
                op[(c0    ) * HW + prow + 8] = acc[mt][j][2];
                op[(c0 + 1) * HW + prow + 8] = acc[mt][j][3];
            }
        }
    }

    // ---- fused BN partial stats (deterministic) ----
    {
        float ps[8], pq[8];
        #pragma unroll
        for (int j = 0; j < 4; j++) {
            float s0v = 0.f, s1v = 0.f, q0v = 0.f, q1v = 0.f;
            #pragma unroll
            for (int mt = 0; mt < 2; mt++) {
                float a = acc[mt][j][0], bb = acc[mt][j][1];
                float cvv = acc[mt][j][2], dv = acc[mt][j][3];
                s0v += a + cvv;          s1v += bb + dv;
                q0v += a*a + cvv*cvv;    q1v += bb*bb + dv*dv;
            }
            ps[2*j] = s0v; ps[2*j+1] = s1v;
            pq[2*j] = q0v; pq[2*j+1] = q1v;
        }
        #pragma unroll
        for (int v = 0; v < 8; v++) {
            #pragma unroll
            for (int off = 16; off >= 4; off >>= 1) {
                ps[v] += __shfl_down_sync(0xffffffffu, ps[v], off);
                pq[v] += __shfl_down_sync(0xffffffffu, pq[v], off);
            }
        }
        float* sred = (float*)sm;   // smem free after last tap sync
        if (lid < 4) {
            float* row = sred + wid*64 + lid*16;
            #pragma unroll
            for (int j = 0; j < 4; j++) {
                row[j*4 + 0] = ps[2*j];
                row[j*4 + 1] = ps[2*j + 1];
                row[j*4 + 2] = pq[2*j];
                row[j*4 + 3] = pq[2*j + 1];
            }
        }
        __syncthreads();
        if (tid < 128) {
            int c = tid >> 1, isq = tid & 1;
            int nw2 = c >> 5, local = c & 31;
            int j = local >> 3, l = (local & 7) >> 1, pair = local & 1;
            int idx = l*16 + j*4 + pair + (isq ? 2 : 0);
            float v = sred[(nw2*4 + 0)*64 + idx] + sred[(nw2*4 + 1)*64 + idx]
                    + sred[(nw2*4 + 2)*64 + idx] + sred[(nw2*4 + 3)*64 + idx];
            if (isq) g_bq[c*NBLK + blockIdx.x] = v;
            else     g_bs[c*NBLK + blockIdx.x] = v;
        }
    }
}

// ---------------------------------------------------------------------------
// Finalize BN: one block per channel, reduce 800 partials (deterministic)
// ---------------------------------------------------------------------------
__global__ void k_finalize(const float* __restrict__ gamma,
                           const float* __restrict__ beta) {
    int c = blockIdx.x;
    __shared__ float rs[256], rq[256];
    float s = 0.f, q = 0.f;
    for (int i = threadIdx.x; i < NBLK; i += 256) {
        s += g_bs[c*NBLK + i];
        q += g_bq[c*NBLK + i];
    }
    rs[threadIdx.x] = s; rq[threadIdx.x] = q;
    __syncthreads();
    for (int st = 128; st > 0; st >>= 1) {
        if (threadIdx.x < st) {
            rs[threadIdx.x] += rs[threadIdx.x + st];
            rq[threadIdx.x] += rq[threadIdx.x + st];
        }
        __syncthreads();
    }
    if (threadIdx.x == 0) {
        float inv_n = 1.f / (float)(BB * HW);
        float mean = rs[0] * inv_n;
        float var  = rq[0] * inv_n - mean * mean;
        float sc = gamma[c] * rsqrtf(var + EPSV);
        g_scale[c] = sc;
        g_shift[c] = beta[c] - mean * sc;
    }
}

__global__ void k_bnrelu(float* __restrict__ out) {
    int idx = blockIdx.x * 256 + threadIdx.x;
    int c = (idx / (HW / 4)) & 63;
    float sc = g_scale[c], sh = g_shift[c];
    float4 v = ((float4*)out)[idx];
    v.x = fmaxf(0.f, v.x * sc + sh);
    v.y = fmaxf(0.f, v.y * sc + sh);
    v.z = fmaxf(0.f, v.z * sc + sh);
    v.w = fmaxf(0.f, v.w * sc + sh);
    ((float4*)out)[idx] = v;
}

// ---------------------------------------------------------------------------
extern "C" void kernel_launch(void* const* d_in, const int* in_sizes, int n_in,
                              void* d_out, int out_size) {
    const float* x     = (const float*)d_in[0];
    const float* d     = (const float*)d_in[1];
    const float* ow    = (const float*)d_in[2];
    const float* cw    = (const float*)d_in[3];
    const float* gamma = (const float*)d_in[4];
    const float* beta  = (const float*)d_in[5];
    float* out = (float*)d_out;
    float* outoff = (out_size >= OUT_MAIN + OUT_OFF) ? (out + OUT_MAIN) : nullptr;

    cudaFuncSetAttribute(k_deform, cudaFuncAttributeMaxDynamicSharedMemorySize,
                         SM_SIZE);
    cudaFuncSetAttribute(k_offmma, cudaFuncAttributeMaxDynamicSharedMemorySize,
                         OSM_SIZE);

    k_transpose<<<dim3(10, BB * HH, 2), dim3(32, 8)>>>(x, d);
    k_wsplit<<<(K2 * CC * COUT + 255) / 256, 256>>>(cw);
    k_owsplit<<<(K2 * OFFC * 32 + 255) / 256, 256>>>(ow);
    k_offmma<<<400, 256, OSM_SIZE>>>(outoff);
    k_deform<<<NBLK, 256, SM_SIZE>>>(out);
    k_finalize<<<COUT, 256>>>(gamma, beta);
    k_bnrelu<<<OUT_MAIN / 4 / 256, 256>>>(out);
}